// round 1
// baseline (speedup 1.0000x reference)
#include <cuda_runtime.h>
#include <math.h>

#define N_NODES_MAX 100000
#define N_EDGES_MAX 3200000

// Scratch (device globals: no allocation allowed in kernel_launch)
__device__ __align__(128) float  g_deg[N_NODES_MAX];          // deg, then dis (in-place)
__device__ __align__(128) float4 g_h1[N_NODES_MAX * 4];       // h1 = x@W1  (16 f32/node)
__device__ __align__(128) float4 g_agg1[N_NODES_MAX * 4];     // agg1, then h1r (in-place)
__device__ __align__(128) float  g_ewc[N_EDGES_MAX];          // compact edge weight
__device__ __align__(128) float  g_norm[N_EDGES_MAX];         // per-edge norm coefficient
__device__ float g_acc[16];                                   // layer-2 global 16-vec reduction

__device__ __forceinline__ void red4(float4* p, float a, float b, float c, float d) {
    asm volatile("red.global.add.v4.f32 [%0], {%1,%2,%3,%4};"
                 :: "l"(p), "f"(a), "f"(b), "f"(c), "f"(d) : "memory");
}

// ---------------------------------------------------------------------------
// Pass 1: deg=1 (self loop), agg1=0, h1 = x@W1, zero g_acc
// ---------------------------------------------------------------------------
__global__ void k_init(const float* __restrict__ x, const float* __restrict__ W1, int N) {
    __shared__ float sW[80];
    if (threadIdx.x < 80) sW[threadIdx.x] = W1[threadIdx.x];
    __syncthreads();
    if (blockIdx.x == 0 && threadIdx.x < 16) g_acc[threadIdx.x] = 0.f;
    int i = blockIdx.x * blockDim.x + threadIdx.x;
    if (i >= N) return;
    g_deg[i] = 1.0f;
    float xv[5];
#pragma unroll
    for (int k = 0; k < 5; k++) xv[k] = x[i * 5 + k];
    float h[16];
#pragma unroll
    for (int c = 0; c < 16; c++) h[c] = 0.f;
#pragma unroll
    for (int k = 0; k < 5; k++)
#pragma unroll
        for (int c = 0; c < 16; c++) h[c] = fmaf(xv[k], sW[k * 16 + c], h[c]);
    float4 z = make_float4(0.f, 0.f, 0.f, 0.f);
#pragma unroll
    for (int j = 0; j < 4; j++) {
        g_h1[i * 4 + j] = make_float4(h[4 * j], h[4 * j + 1], h[4 * j + 2], h[4 * j + 3]);
        g_agg1[i * 4 + j] = z;
    }
}

// ---------------------------------------------------------------------------
// Pass 2: deg[dst] += ew; also compact edge weights
// ---------------------------------------------------------------------------
__global__ void k_deg(const int* __restrict__ ei, const float* __restrict__ ea, int E) {
    int e = blockIdx.x * blockDim.x + threadIdx.x;
    if (e >= E) return;
    int d = ei[E + e];
    float w = ea[(size_t)4 * e];
    g_ewc[e] = w;
    atomicAdd(&g_deg[d], w);
}

// ---------------------------------------------------------------------------
// Pass 3: dis = rsqrt(deg)  (deg >= 1 always due to self-loop)
// ---------------------------------------------------------------------------
__global__ void k_dis(int N) {
    int i = blockIdx.x * blockDim.x + threadIdx.x;
    if (i < N) g_deg[i] = rsqrtf(g_deg[i]);
}

// ---------------------------------------------------------------------------
// Pass 4: layer-1 edge scatter: agg1[dst] += h1[src] * norm; cache norm
// ---------------------------------------------------------------------------
__global__ void k_agg1(const int* __restrict__ ei, int E) {
    int e = blockIdx.x * blockDim.x + threadIdx.x;
    if (e >= E) return;
    int s = ei[e];
    int d = ei[E + e];
    float c = g_deg[s] * g_ewc[e] * g_deg[d];
    g_norm[e] = c;
    const float4* hp = &g_h1[(size_t)s * 4];
    float4* op = &g_agg1[(size_t)d * 4];
#pragma unroll
    for (int j = 0; j < 4; j++) {
        float4 h = hp[j];
        red4(op + j, h.x * c, h.y * c, h.z * c, h.w * c);
    }
}

// ---------------------------------------------------------------------------
// Pass 5: h1r = relu(agg1 + h1*dis^2 + b1) (in-place into g_agg1);
//         also accumulate layer-2 self-loop term h1r*dis^2 into g_acc
// ---------------------------------------------------------------------------
__global__ void k_post(const float* __restrict__ b1, int N) {
    int i = blockIdx.x * blockDim.x + threadIdx.x;
    float v[16];
#pragma unroll
    for (int c = 0; c < 16; c++) v[c] = 0.f;
    if (i < N) {
        float di = g_deg[i];
        float d2 = di * di;
#pragma unroll
        for (int j = 0; j < 4; j++) {
            float4 a = g_agg1[i * 4 + j];
            float4 h = g_h1[i * 4 + j];
            float4 r;
            r.x = fmaxf(a.x + h.x * d2 + b1[4 * j + 0], 0.f);
            r.y = fmaxf(a.y + h.y * d2 + b1[4 * j + 1], 0.f);
            r.z = fmaxf(a.z + h.z * d2 + b1[4 * j + 2], 0.f);
            r.w = fmaxf(a.w + h.w * d2 + b1[4 * j + 3], 0.f);
            g_agg1[i * 4 + j] = r;
            v[4 * j + 0] = r.x * d2;
            v[4 * j + 1] = r.y * d2;
            v[4 * j + 2] = r.z * d2;
            v[4 * j + 3] = r.w * d2;
        }
    }
    // warp -> block -> global reduction
#pragma unroll
    for (int c = 0; c < 16; c++)
#pragma unroll
        for (int m = 16; m > 0; m >>= 1) v[c] += __shfl_xor_sync(0xffffffffu, v[c], m);
    __shared__ float sb[16];
    if (threadIdx.x < 16) sb[threadIdx.x] = 0.f;
    __syncthreads();
    if ((threadIdx.x & 31) == 0) {
#pragma unroll
        for (int c = 0; c < 16; c++) atomicAdd(&sb[c], v[c]);
    }
    __syncthreads();
    if (threadIdx.x < 16) atomicAdd(&g_acc[threadIdx.x], sb[threadIdx.x]);
}

// ---------------------------------------------------------------------------
// Pass 6: layer-2 edge reduction: g_acc += sum_e h1r[src]*norm_e
// ---------------------------------------------------------------------------
__global__ void k_red2(const int* __restrict__ ei, int E) {
    float acc[16];
#pragma unroll
    for (int c = 0; c < 16; c++) acc[c] = 0.f;
    int stride = gridDim.x * blockDim.x;
    for (int e = blockIdx.x * blockDim.x + threadIdx.x; e < E; e += stride) {
        int s = ei[e];
        float c = g_norm[e];
        const float4* hp = &g_agg1[(size_t)s * 4];
#pragma unroll
        for (int j = 0; j < 4; j++) {
            float4 h = hp[j];
            acc[4 * j + 0] = fmaf(h.x, c, acc[4 * j + 0]);
            acc[4 * j + 1] = fmaf(h.y, c, acc[4 * j + 1]);
            acc[4 * j + 2] = fmaf(h.z, c, acc[4 * j + 2]);
            acc[4 * j + 3] = fmaf(h.w, c, acc[4 * j + 3]);
        }
    }
#pragma unroll
    for (int c = 0; c < 16; c++)
#pragma unroll
        for (int m = 16; m > 0; m >>= 1) acc[c] += __shfl_xor_sync(0xffffffffu, acc[c], m);
    __shared__ float sb[16];
    if (threadIdx.x < 16) sb[threadIdx.x] = 0.f;
    __syncthreads();
    if ((threadIdx.x & 31) == 0) {
#pragma unroll
        for (int c = 0; c < 16; c++) atomicAdd(&sb[c], acc[c]);
    }
    __syncthreads();
    if (threadIdx.x < 16) atomicAdd(&g_acc[threadIdx.x], sb[threadIdx.x]);
}

// ---------------------------------------------------------------------------
// Pass 7: state = (g_acc/N)@W2 + b2; MLP 4->128->64->50; softmax
// ---------------------------------------------------------------------------
__global__ void k_final(const float* __restrict__ W2, const float* __restrict__ b2,
                        const float* __restrict__ pW1, const float* __restrict__ pb1,
                        const float* __restrict__ pW2, const float* __restrict__ pb2,
                        const float* __restrict__ pW3, const float* __restrict__ pb3,
                        float* __restrict__ out, int N) {
    __shared__ float st[4];
    __shared__ float z1[128];
    __shared__ float z2[64];
    __shared__ float lg[50];
    __shared__ float ms[2];
    int t = threadIdx.x;
    if (t < 4) {
        float s = 0.f;
#pragma unroll
        for (int k = 0; k < 16; k++) s = fmaf(g_acc[k], W2[k * 4 + t], s);
        st[t] = s / (float)N + b2[t];
    }
    __syncthreads();
    {
        float vv = pb1[t];
#pragma unroll
        for (int j = 0; j < 4; j++) vv = fmaf(st[j], pW1[j * 128 + t], vv);
        z1[t] = fmaxf(vv, 0.f);
    }
    __syncthreads();
    if (t < 64) {
        float vv = pb2[t];
#pragma unroll 8
        for (int k = 0; k < 128; k++) vv = fmaf(z1[k], pW2[k * 64 + t], vv);
        z2[t] = fmaxf(vv, 0.f);
    }
    __syncthreads();
    if (t < 50) {
        float vv = pb3[t];
#pragma unroll 8
        for (int k = 0; k < 64; k++) vv = fmaf(z2[k], pW3[k * 50 + t], vv);
        lg[t] = vv;
    }
    __syncthreads();
    if (t == 0) {
        float m = lg[0];
        for (int k = 1; k < 50; k++) m = fmaxf(m, lg[k]);
        float s = 0.f;
        for (int k = 0; k < 50; k++) s += expf(lg[k] - m);
        ms[0] = m;
        ms[1] = s;
    }
    __syncthreads();
    if (t < 50) out[t] = expf(lg[t] - ms[0]) / ms[1];
}

// ---------------------------------------------------------------------------
extern "C" void kernel_launch(void* const* d_in, const int* in_sizes, int n_in,
                              void* d_out, int out_size) {
    const float* x   = (const float*)d_in[0];
    const int*   ei  = (const int*)  d_in[1];
    const float* ea  = (const float*)d_in[2];
    const float* W1  = (const float*)d_in[3];
    const float* b1  = (const float*)d_in[4];
    const float* W2  = (const float*)d_in[5];
    const float* b2  = (const float*)d_in[6];
    const float* pW1 = (const float*)d_in[7];
    const float* pb1 = (const float*)d_in[8];
    const float* pW2 = (const float*)d_in[9];
    const float* pb2 = (const float*)d_in[10];
    const float* pW3 = (const float*)d_in[11];
    const float* pb3 = (const float*)d_in[12];
    float* out = (float*)d_out;

    int N = in_sizes[0] / 5;
    int E = in_sizes[1] / 2;
    const int TB = 256;
    int nb = (N + TB - 1) / TB;
    int eb = (E + TB - 1) / TB;

    k_init<<<nb, TB>>>(x, W1, N);
    k_deg<<<eb, TB>>>(ei, ea, E);
    k_dis<<<nb, TB>>>(N);
    k_agg1<<<eb, TB>>>(ei, E);
    k_post<<<nb, TB>>>(b1, N);
    k_red2<<<1184, TB>>>(ei, E);
    k_final<<<1, 128>>>(W2, b2, pW1, pb1, pW2, pb2, pW3, pb3, out, N);
}

// round 2
// speedup vs baseline: 1.2353x; 1.2353x over previous
#include <cuda_runtime.h>
#include <math.h>

#define N_NODES_MAX 100000
#define N_EDGES_MAX 3200000

// Scratch (device globals: no allocation allowed in kernel_launch)
__device__ __align__(128) float  g_deg[N_NODES_MAX];          // deg, then dis (in-place)
__device__ __align__(128) float  g_w2[N_NODES_MAX];           // sum over out-edges of ewc*dis[dst]
__device__ __align__(128) float4 g_h1[N_NODES_MAX * 4];       // h1 = x@W1, then h1s = h1*dis (in-place)
__device__ __align__(128) float4 g_agg1[N_NODES_MAX * 4];     // layer-1 message accumulator
__device__ __align__(128) float  g_ewc[N_EDGES_MAX];          // compact edge weight
__device__ float g_acc[16];                                   // layer-2 global 16-vec reduction

__device__ __forceinline__ void red4(float4* p, float a, float b, float c, float d) {
    asm volatile("red.global.add.v4.f32 [%0], {%1,%2,%3,%4};"
                 :: "l"(p), "f"(a), "f"(b), "f"(c), "f"(d) : "memory");
}
__device__ __forceinline__ void red1(float* p, float a) {
    asm volatile("red.global.add.f32 [%0], %1;" :: "l"(p), "f"(a) : "memory");
}

// ---------------------------------------------------------------------------
// Pass 1: deg=1 (self loop), w2=0, agg1=0, h1 = x@W1, zero g_acc
// ---------------------------------------------------------------------------
__global__ void k_init(const float* __restrict__ x, const float* __restrict__ W1, int N) {
    __shared__ float sW[80];
    if (threadIdx.x < 80) sW[threadIdx.x] = W1[threadIdx.x];
    __syncthreads();
    if (blockIdx.x == 0 && threadIdx.x < 16) g_acc[threadIdx.x] = 0.f;
    int i = blockIdx.x * blockDim.x + threadIdx.x;
    if (i >= N) return;
    g_deg[i] = 1.0f;
    g_w2[i] = 0.0f;
    float xv[5];
#pragma unroll
    for (int k = 0; k < 5; k++) xv[k] = x[i * 5 + k];
    float h[16];
#pragma unroll
    for (int c = 0; c < 16; c++) h[c] = 0.f;
#pragma unroll
    for (int k = 0; k < 5; k++)
#pragma unroll
        for (int c = 0; c < 16; c++) h[c] = fmaf(xv[k], sW[k * 16 + c], h[c]);
    float4 z = make_float4(0.f, 0.f, 0.f, 0.f);
#pragma unroll
    for (int j = 0; j < 4; j++) {
        g_h1[i * 4 + j] = make_float4(h[4 * j], h[4 * j + 1], h[4 * j + 2], h[4 * j + 3]);
        g_agg1[i * 4 + j] = z;
    }
}

// ---------------------------------------------------------------------------
// Pass 2: deg[dst] += ew; compact edge weights
// ---------------------------------------------------------------------------
__global__ void k_deg(const int* __restrict__ ei, const float* __restrict__ ea, int E) {
    int e = blockIdx.x * blockDim.x + threadIdx.x;
    if (e >= E) return;
    int d = ei[E + e];
    float w = ea[(size_t)4 * e];
    g_ewc[e] = w;
    atomicAdd(&g_deg[d], w);
}

// ---------------------------------------------------------------------------
// Pass 3: dis = rsqrt(deg); h1s = h1 * dis (premultiply source-side norm)
// ---------------------------------------------------------------------------
__global__ void k_dis(int N) {
    int i = blockIdx.x * blockDim.x + threadIdx.x;
    if (i >= N) return;
    float di = rsqrtf(g_deg[i]);
    g_deg[i] = di;
#pragma unroll
    for (int j = 0; j < 4; j++) {
        float4 h = g_h1[i * 4 + j];
        h.x *= di; h.y *= di; h.z *= di; h.w *= di;
        g_h1[i * 4 + j] = h;
    }
}

// ---------------------------------------------------------------------------
// Pass 4: per edge: c = ewc * dis[dst];
//         agg1[dst] += h1s[src] * c   (full symmetric norm: h1s has dis[src])
//         w2[src]   += c              (layer-2 coefficient accumulation)
// ---------------------------------------------------------------------------
__global__ void k_agg1(const int* __restrict__ ei, int E) {
    int e = blockIdx.x * blockDim.x + threadIdx.x;
    if (e >= E) return;
    int s = ei[e];
    int d = ei[E + e];
    float c = g_ewc[e] * g_deg[d];
    const float4* hp = &g_h1[(size_t)s * 4];
    float4* op = &g_agg1[(size_t)d * 4];
#pragma unroll
    for (int j = 0; j < 4; j++) {
        float4 h = hp[j];
        red4(op + j, h.x * c, h.y * c, h.z * c, h.w * c);
    }
    red1(&g_w2[s], c);
}

// ---------------------------------------------------------------------------
// Pass 5: h1r = relu(agg1 + h1s*dis + b1)  [h1s*dis == h1*dis^2 self-loop]
//         acc += h1r * (dis*w2 + dis^2)    [layer-2 + mean-pool, factored]
// ---------------------------------------------------------------------------
__global__ void k_post(const float* __restrict__ b1, int N) {
    int i = blockIdx.x * blockDim.x + threadIdx.x;
    float v[16];
#pragma unroll
    for (int c = 0; c < 16; c++) v[c] = 0.f;
    if (i < N) {
        float di = g_deg[i];
        float coef = fmaf(di, g_w2[i], di * di);
#pragma unroll
        for (int j = 0; j < 4; j++) {
            float4 a = g_agg1[i * 4 + j];
            float4 h = g_h1[i * 4 + j];
            v[4 * j + 0] = fmaxf(fmaf(h.x, di, a.x) + b1[4 * j + 0], 0.f) * coef;
            v[4 * j + 1] = fmaxf(fmaf(h.y, di, a.y) + b1[4 * j + 1], 0.f) * coef;
            v[4 * j + 2] = fmaxf(fmaf(h.z, di, a.z) + b1[4 * j + 2], 0.f) * coef;
            v[4 * j + 3] = fmaxf(fmaf(h.w, di, a.w) + b1[4 * j + 3], 0.f) * coef;
        }
    }
    // warp -> block -> global reduction
#pragma unroll
    for (int c = 0; c < 16; c++)
#pragma unroll
        for (int m = 16; m > 0; m >>= 1) v[c] += __shfl_xor_sync(0xffffffffu, v[c], m);
    __shared__ float sb[16];
    if (threadIdx.x < 16) sb[threadIdx.x] = 0.f;
    __syncthreads();
    if ((threadIdx.x & 31) == 0) {
#pragma unroll
        for (int c = 0; c < 16; c++) atomicAdd(&sb[c], v[c]);
    }
    __syncthreads();
    if (threadIdx.x < 16) atomicAdd(&g_acc[threadIdx.x], sb[threadIdx.x]);
}

// ---------------------------------------------------------------------------
// Pass 6: state = (g_acc/N)@W2 + b2; MLP 4->128->64->50; softmax
// ---------------------------------------------------------------------------
__global__ void k_final(const float* __restrict__ W2, const float* __restrict__ b2,
                        const float* __restrict__ pW1, const float* __restrict__ pb1,
                        const float* __restrict__ pW2, const float* __restrict__ pb2,
                        const float* __restrict__ pW3, const float* __restrict__ pb3,
                        float* __restrict__ out, int N) {
    __shared__ float st[4];
    __shared__ float z1[128];
    __shared__ float z2[64];
    __shared__ float lg[50];
    __shared__ float ms[2];
    int t = threadIdx.x;
    if (t < 4) {
        float s = 0.f;
#pragma unroll
        for (int k = 0; k < 16; k++) s = fmaf(g_acc[k], W2[k * 4 + t], s);
        st[t] = s / (float)N + b2[t];
    }
    __syncthreads();
    {
        float vv = pb1[t];
#pragma unroll
        for (int j = 0; j < 4; j++) vv = fmaf(st[j], pW1[j * 128 + t], vv);
        z1[t] = fmaxf(vv, 0.f);
    }
    __syncthreads();
    if (t < 64) {
        float vv = pb2[t];
#pragma unroll 8
        for (int k = 0; k < 128; k++) vv = fmaf(z1[k], pW2[k * 64 + t], vv);
        z2[t] = fmaxf(vv, 0.f);
    }
    __syncthreads();
    if (t < 50) {
        float vv = pb3[t];
#pragma unroll 8
        for (int k = 0; k < 64; k++) vv = fmaf(z2[k], pW3[k * 50 + t], vv);
        lg[t] = vv;
    }
    __syncthreads();
    if (t == 0) {
        float m = lg[0];
        for (int k = 1; k < 50; k++) m = fmaxf(m, lg[k]);
        float s = 0.f;
        for (int k = 0; k < 50; k++) s += expf(lg[k] - m);
        ms[0] = m;
        ms[1] = s;
    }
    __syncthreads();
    if (t < 50) out[t] = expf(lg[t] - ms[0]) / ms[1];
}

// ---------------------------------------------------------------------------
extern "C" void kernel_launch(void* const* d_in, const int* in_sizes, int n_in,
                              void* d_out, int out_size) {
    const float* x   = (const float*)d_in[0];
    const int*   ei  = (const int*)  d_in[1];
    const float* ea  = (const float*)d_in[2];
    const float* W1  = (const float*)d_in[3];
    const float* b1  = (const float*)d_in[4];
    const float* W2  = (const float*)d_in[5];
    const float* b2  = (const float*)d_in[6];
    const float* pW1 = (const float*)d_in[7];
    const float* pb1 = (const float*)d_in[8];
    const float* pW2 = (const float*)d_in[9];
    const float* pb2 = (const float*)d_in[10];
    const float* pW3 = (const float*)d_in[11];
    const float* pb3 = (const float*)d_in[12];
    float* out = (float*)d_out;

    int N = in_sizes[0] / 5;
    int E = in_sizes[1] / 2;
    const int TB = 256;
    int nb = (N + TB - 1) / TB;
    int eb = (E + TB - 1) / TB;

    k_init<<<nb, TB>>>(x, W1, N);
    k_deg<<<eb, TB>>>(ei, ea, E);
    k_dis<<<nb, TB>>>(N);
    k_agg1<<<eb, TB>>>(ei, E);
    k_post<<<nb, TB>>>(b1, N);
    k_final<<<1, 128>>>(W2, b2, pW1, pb1, pW2, pb2, pW3, pb3, out, N);
}

// round 4
// speedup vs baseline: 1.8400x; 1.4894x over previous
#include <cuda_runtime.h>
#include <math.h>

#define N_NODES_MAX 100000
#define N_EDGES_MAX 3200000

// Scratch (device globals: no allocation in kernel_launch)
__device__ __align__(128) float  g_deg[N_NODES_MAX];         // deg accum, then dis (in place)
__device__ __align__(128) float  g_w2[N_NODES_MAX];          // sum over out-edges of ewc*dis[dst]
__device__ __align__(128) float4 g_xs[N_NODES_MAX * 2];      // x*dis padded to 32B/node
__device__ __align__(128) float4 g_aggx[N_NODES_MAX * 2];    // 5-dim edge accumulator, 32B/node
__device__ __align__(128) float  g_ewc[N_EDGES_MAX];         // compact edge weight
__device__ float g_acc[16];                                  // final 16-vec reduction

__device__ __forceinline__ void red4(float4* p, float a, float b, float c, float d) {
    asm volatile("red.global.add.v4.f32 [%0], {%1,%2,%3,%4};"
                 :: "l"(p), "f"(a), "f"(b), "f"(c), "f"(d) : "memory");
}
__device__ __forceinline__ void red1(float* p, float a) {
    asm volatile("red.global.add.f32 [%0], %1;" :: "l"(p), "f"(a) : "memory");
}

// ---------------------------------------------------------------------------
// Pass 1: zero deg, w2, aggx, acc
// ---------------------------------------------------------------------------
__global__ void k_zero(int N) {
    int i = blockIdx.x * blockDim.x + threadIdx.x;
    if (blockIdx.x == 0 && threadIdx.x < 16) g_acc[threadIdx.x] = 0.f;
    if (i >= N) return;
    g_deg[i] = 0.f;
    g_w2[i] = 0.f;
    float4 z = make_float4(0.f, 0.f, 0.f, 0.f);
    g_aggx[i * 2] = z;
    g_aggx[i * 2 + 1] = z;
}

// ---------------------------------------------------------------------------
// Pass 2: deg[dst] += ew; compact edge weights
// ---------------------------------------------------------------------------
__global__ void k_deg(const int* __restrict__ ei, const float* __restrict__ ea, int E) {
    int e = blockIdx.x * blockDim.x + threadIdx.x;
    if (e >= E) return;
    int d = ei[E + e];
    float w = ea[(size_t)4 * e];
    g_ewc[e] = w;
    atomicAdd(&g_deg[d], w);
}

// ---------------------------------------------------------------------------
// Pass 3: dis = rsqrt(1 + deg); xs = x * dis (padded to 8 floats)
// ---------------------------------------------------------------------------
__global__ void k_dis(const float* __restrict__ x, int N) {
    int i = blockIdx.x * blockDim.x + threadIdx.x;
    if (i >= N) return;
    float di = rsqrtf(1.0f + g_deg[i]);
    g_deg[i] = di;
    float x0 = x[i * 5 + 0], x1 = x[i * 5 + 1], x2 = x[i * 5 + 2];
    float x3 = x[i * 5 + 3], x4 = x[i * 5 + 4];
    g_xs[i * 2]     = make_float4(x0 * di, x1 * di, x2 * di, x3 * di);
    g_xs[i * 2 + 1] = make_float4(x4 * di, 0.f, 0.f, 0.f);
}

// ---------------------------------------------------------------------------
// Pass 4: per edge: c = ewc * dis[dst]
//   aggx[dst] += xs[src] * c   (5 floats: red.v4 + red1, one 32B sector)
//   w2[src]   += c
// ---------------------------------------------------------------------------
__global__ void k_agg1(const int* __restrict__ ei, int E) {
    int e = blockIdx.x * blockDim.x + threadIdx.x;
    if (e >= E) return;
    int s = ei[e];
    int d = ei[E + e];
    float c = g_ewc[e] * g_deg[d];
    float4 m0 = g_xs[(size_t)s * 2];
    float  m4 = ((const float*)&g_xs[(size_t)s * 2 + 1])[0];
    float4* op = &g_aggx[(size_t)d * 2];
    red4(op, m0.x * c, m0.y * c, m0.z * c, m0.w * c);
    red1((float*)(op + 1), m4 * c);
    red1(&g_w2[s], c);
}

// ---------------------------------------------------------------------------
// Pass 5: per node:
//   a5 = aggx + x*dis^2  (self loop);  h = relu(a5 @ W1 + b1)  (5 -> 16)
//   acc += h * (dis*w2 + dis^2)
// ---------------------------------------------------------------------------
__global__ void k_post(const float* __restrict__ x, const float* __restrict__ W1,
                       const float* __restrict__ b1, int N) {
    __shared__ float sW[80];
    __shared__ float sB[16];
    if (threadIdx.x < 80) sW[threadIdx.x] = W1[threadIdx.x];
    if (threadIdx.x < 16) sB[threadIdx.x] = b1[threadIdx.x];
    __syncthreads();
    int i = blockIdx.x * blockDim.x + threadIdx.x;
    float v[16];
#pragma unroll
    for (int c = 0; c < 16; c++) v[c] = 0.f;
    if (i < N) {
        float di = g_deg[i];
        float d2 = di * di;
        float coef = fmaf(di, g_w2[i], d2);
        float4 a0 = g_aggx[i * 2];
        float  a4 = ((const float*)&g_aggx[i * 2 + 1])[0];
        float a5[5];
        a5[0] = fmaf(x[i * 5 + 0], d2, a0.x);
        a5[1] = fmaf(x[i * 5 + 1], d2, a0.y);
        a5[2] = fmaf(x[i * 5 + 2], d2, a0.z);
        a5[3] = fmaf(x[i * 5 + 3], d2, a0.w);
        a5[4] = fmaf(x[i * 5 + 4], d2, a4);
#pragma unroll
        for (int c = 0; c < 16; c++) {
            float h = sB[c];
#pragma unroll
            for (int k = 0; k < 5; k++) h = fmaf(a5[k], sW[k * 16 + c], h);
            v[c] = fmaxf(h, 0.f) * coef;
        }
    }
    // warp -> block -> global reduction
#pragma unroll
    for (int c = 0; c < 16; c++)
#pragma unroll
        for (int m = 16; m > 0; m >>= 1) v[c] += __shfl_xor_sync(0xffffffffu, v[c], m);
    __shared__ float sb[16];
    if (threadIdx.x < 16) sb[threadIdx.x] = 0.f;
    __syncthreads();
    if ((threadIdx.x & 31) == 0) {
#pragma unroll
        for (int c = 0; c < 16; c++) atomicAdd(&sb[c], v[c]);
    }
    __syncthreads();
    if (threadIdx.x < 16) atomicAdd(&g_acc[threadIdx.x], sb[threadIdx.x]);
}

// ---------------------------------------------------------------------------
// Pass 6: state = (g_acc/N)@W2 + b2; MLP 4->128->64->50; softmax
// ---------------------------------------------------------------------------
__global__ void k_final(const float* __restrict__ W2, const float* __restrict__ b2,
                        const float* __restrict__ pW1, const float* __restrict__ pb1,
                        const float* __restrict__ pW2, const float* __restrict__ pb2,
                        const float* __restrict__ pW3, const float* __restrict__ pb3,
                        float* __restrict__ out, int N) {
    __shared__ float st[4];
    __shared__ float z1[128];
    __shared__ float z2[64];
    __shared__ float lg[50];
    __shared__ float ms[2];
    int t = threadIdx.x;
    if (t < 4) {
        float s = 0.f;
#pragma unroll
        for (int k = 0; k < 16; k++) s = fmaf(g_acc[k], W2[k * 4 + t], s);
        st[t] = s / (float)N + b2[t];
    }
    __syncthreads();
    {
        float vv = pb1[t];
#pragma unroll
        for (int j = 0; j < 4; j++) vv = fmaf(st[j], pW1[j * 128 + t], vv);
        z1[t] = fmaxf(vv, 0.f);
    }
    __syncthreads();
    if (t < 64) {
        float vv = pb2[t];
#pragma unroll 8
        for (int k = 0; k < 128; k++) vv = fmaf(z1[k], pW2[k * 64 + t], vv);
        z2[t] = fmaxf(vv, 0.f);
    }
    __syncthreads();
    if (t < 50) {
        float vv = pb3[t];
#pragma unroll 8
        for (int k = 0; k < 64; k++) vv = fmaf(z2[k], pW3[k * 50 + t], vv);
        lg[t] = vv;
    }
    __syncthreads();
    if (t == 0) {
        float m = lg[0];
        for (int k = 1; k < 50; k++) m = fmaxf(m, lg[k]);
        float s = 0.f;
        for (int k = 0; k < 50; k++) s += expf(lg[k] - m);
        ms[0] = m;
        ms[1] = s;
    }
    __syncthreads();
    if (t < 50) out[t] = expf(lg[t] - ms[0]) / ms[1];
}

// ---------------------------------------------------------------------------
extern "C" void kernel_launch(void* const* d_in, const int* in_sizes, int n_in,
                              void* d_out, int out_size) {
    const float* x   = (const float*)d_in[0];
    const int*   ei  = (const int*)  d_in[1];
    const float* ea  = (const float*)d_in[2];
    const float* W1  = (const float*)d_in[3];
    const float* b1  = (const float*)d_in[4];
    const float* W2  = (const float*)d_in[5];
    const float* b2  = (const float*)d_in[6];
    const float* pW1 = (const float*)d_in[7];
    const float* pb1 = (const float*)d_in[8];
    const float* pW2 = (const float*)d_in[9];
    const float* pb2 = (const float*)d_in[10];
    const float* pW3 = (const float*)d_in[11];
    const float* pb3 = (const float*)d_in[12];
    float* out = (float*)d_out;

    int N = in_sizes[0] / 5;
    int E = in_sizes[1] / 2;
    const int TB = 256;
    int nb = (N + TB - 1) / TB;
    int eb = (E + TB - 1) / TB;

    k_zero<<<nb, TB>>>(N);
    k_deg<<<eb, TB>>>(ei, ea, E);
    k_dis<<<nb, TB>>>(x, N);
    k_agg1<<<eb, TB>>>(ei, E);
    k_post<<<nb, TB>>>(x, W1, b1, N);
    k_final<<<1, 128>>>(W2, b2, pW1, pb1, pW2, pb2, pW3, pb3, out, N);
}